// round 15
// baseline (speedup 1.0000x reference)
#include <cuda_runtime.h>
#include <cuda_bf16.h>
#include <math.h>
#include <stdint.h>

// HierarchicalDistanceLoss — R15: R14 + true gapless 3-stage cp.async schedule.
// Loop j: wait(tile j) -> ISSUE tile j+2 (slab (j+2)%3 free since iter j-1)
// -> compute tile j. Two groups in flight during every compute phase.
// GRIDB=1024: 4096 warps x exactly 16 tiles (perfect balance), ~7 CTAs/SM.
//   ce[b]  = log(sum exp(logits[b,:])) - logits[b, labels[b]]
//   pred   = argmax (first occurrence); df = dis[lab,pred]+0.5
//   out[0] = mean(ce*df), out[1..B] = df

#define CCOLS 40
#define TPB   128
#define WPB   4                        // warps per block
#define RPW   16                       // rows per warp-tile (2 lanes/row)
#define F4PT  (RPW * 10)               // 160 float4 = 2560 B per stage
#define NSTAGE 3
#define GRIDB 1024                     // 4096 warps -> 65536/4096 = 16 tiles each
#define NW    (GRIDB * WPB)

#define CP_CG16(dst, src) asm volatile("cp.async.cg.shared.global [%0], [%1], 16;" :: "r"(dst), "l"(src) : "memory")
#define CP_COMMIT()       asm volatile("cp.async.commit_group;" ::: "memory")
#define CP_WAIT1()        asm volatile("cp.async.wait_group 1;" ::: "memory")

__device__ float    g_partials[8192];
__device__ unsigned g_count;           // zero-init; last block resets

__global__ void __launch_bounds__(TPB, 7) hier_loss_r15(
    const float* __restrict__ logits,  // [B*40]
    const int*   __restrict__ labels,  // [B]
    const float* __restrict__ dis,     // [40*40]
    float*       __restrict__ out,     // [0] = loss
    float*       __restrict__ df_out,  // [B]
    float invB, int ntiles)            // ntiles = B/16
{
    __shared__ __align__(128) float4 tile[WPB][NSTAGE][F4PT];   // 30720 B
    __shared__ float wsum[WPB];
    __shared__ int   isLast;

    const int tid  = threadIdx.x;
    const int wid  = tid >> 5;
    const int lane = tid & 31;
    const int half = lane & 1;         // 0: cols 0-19, 1: cols 20-39
    const int rrow = lane >> 1;        // row within tile (0..15)
    const int bid  = blockIdx.x;
    const int gw   = bid * WPB + wid;  // global warp id

    const int nmine = (ntiles - gw + NW - 1) / NW;   // 16 exactly

    const uint32_t t0 = (uint32_t)__cvta_generic_to_shared(&tile[wid][0][0]);

    auto issue = [&](int j) {          // warp-cooperative, coalesced
        const int s = j % NSTAGE;
        const long long t = gw + (long long)j * NW;
        const float4* src = (const float4*)logits + t * F4PT;
        const uint32_t dst = t0 + (uint32_t)s * (F4PT * 16);
        #pragma unroll
        for (int i = 0; i < 5; ++i) {
            int idx = i * 32 + lane;
            CP_CG16(dst + (uint32_t)idx * 16u, src + idx);
        }
    };

    auto lrow = [&](int j) -> long long {     // row owned by even lane, tile j
        return (gw + (long long)j * NW) * RPW + rrow;
    };

    int lab_q0 = 0, lab_q1 = 0, lab_q2 = 0;   // 3-deep label prefetch
    if (nmine > 0) {
        issue(0); CP_COMMIT();
        if (half == 0) lab_q0 = __ldcs(&labels[lrow(0)]);
    }
    if (nmine > 1) {
        issue(1); CP_COMMIT();
        if (half == 0) lab_q1 = __ldcs(&labels[lrow(1)]);
    }

    float acc = 0.0f;

    for (int j = 0; j < nmine; ++j) {
        const int s = j % NSTAGE;

        CP_WAIT1();                    // tile j complete (tile j+1 in flight)
        __syncwarp();                  // cross-lane copy visibility

        // refill BEFORE compute: slab (j+2)%3 last read at iter j-1 -> free
        if (j + 2 < nmine) {
            issue(j + 2);
            if (half == 0) lab_q2 = __ldcs(&labels[lrow(j + 2)]);
        }
        CP_COMMIT();                   // uniform group count per iteration

        // lane covers floats [20*half, 20*half+20) of row rrow
        const float4* r   = &tile[wid][s][rrow * 10 + half * 5];
        const float*  row = (const float*)&tile[wid][s][rrow * 10];
        const int base = 20 * half;

        float m = -INFINITY, sum = 0.0f;
        int   am = base;
        #pragma unroll
        for (int i = 0; i < 5; ++i) {
            float4 v = r[i];
            if (v.x > m) { m = v.x; am = base + 4*i;   }
            if (v.y > m) { m = v.y; am = base + 4*i+1; }
            if (v.z > m) { m = v.z; am = base + 4*i+2; }
            if (v.w > m) { m = v.w; am = base + 4*i+3; }
            sum += (__expf(v.x) + __expf(v.y)) + (__expf(v.z) + __expf(v.w));
        }
        {   // pair merge (xor 1); tie -> smaller index = first occurrence
            float om = __shfl_xor_sync(0xffffffffu, m,  1);
            int   oa = __shfl_xor_sync(0xffffffffu, am, 1);
            if (om > m || (om == m && oa < am)) { m = om; am = oa; }
            sum += __shfl_xor_sync(0xffffffffu, sum, 1);
        }
        const float lse = __logf(sum);

        if (half == 0) {               // even lane finalizes its row
            const int lab = lab_q0;
            const float ce  = lse - row[lab];
            const float dfv = __ldg(&dis[lab * CCOLS + am]) + 0.5f;
            __stcs(&df_out[lrow(j)], dfv);
            acc += ce * dfv;
        }

        lab_q0 = lab_q1; lab_q1 = lab_q2;     // rotate label queue
        // no trailing sync: slab s reads complete above; next write to s is
        // issue(j+3) at iter j+1, after this warp's converged compute of j.
    }

    // ---- block reduction (deterministic) ----
    #pragma unroll
    for (int o = 16; o > 0; o >>= 1)
        acc += __shfl_down_sync(0xffffffffu, acc, o);
    if (lane == 0) wsum[wid] = acc;
    __syncthreads();
    if (tid == 0) {
        g_partials[bid] = (wsum[0] + wsum[1]) + (wsum[2] + wsum[3]);
        __threadfence();
        isLast = (atomicAdd(&g_count, 1u) == (unsigned)(GRIDB - 1));
    }
    __syncthreads();

    // ---- last-block-done final mean: independent unrolled loads ----
    if (isLast) {
        float part[8];                           // 1024/128 = 8
        #pragma unroll
        for (int k = 0; k < 8; ++k)
            part[k] = g_partials[tid + k * TPB];
        float t = 0.0f;
        #pragma unroll
        for (int k = 0; k < 8; ++k) t += part[k];

        #pragma unroll
        for (int o = 16; o > 0; o >>= 1)
            t += __shfl_down_sync(0xffffffffu, t, o);
        __shared__ float fsum[WPB];
        if (lane == 0) fsum[wid] = t;
        __syncthreads();
        if (tid == 0) {
            out[0] = ((fsum[0] + fsum[1]) + (fsum[2] + fsum[3])) * invB;
            g_count = 0;               // reset for graph replay
        }
    }
}

extern "C" void kernel_launch(void* const* d_in, const int* in_sizes, int n_in,
                              void* d_out, int out_size)
{
    const float* logits = (const float*)d_in[0];
    const int*   labels = (const int*)d_in[1];
    const float* dis    = (const float*)d_in[2];
    float* out = (float*)d_out;

    const long long B = (long long)in_sizes[1];     // 1048576
    const int ntiles = (int)(B / RPW);              // 65536

    const int off = out_size - (int)B;              // [loss, df...] layout
    float* dfo = out + (off > 0 ? off : 0);

    hier_loss_r15<<<GRIDB, TPB>>>(logits, labels, dis, out, dfo,
                                  1.0f / (float)B, ntiles);
}

// round 16
// speedup vs baseline: 1.0082x; 1.0082x over previous
#include <cuda_runtime.h>
#include <cuda_bf16.h>
#include <math.h>
#include <stdint.h>

// HierarchicalDistanceLoss — R16 (final): R14 hot path (best measured:
// 32.77us main, 5.42 TB/s) minus the dead trailing __syncwarp.
// Warp-private 2-stage cp.async pipeline, 16-row warp-tiles, 2 lanes/row,
// balanced persistent grid (1366 blocks -> 5464 warps x ~12 tiles),
// labels via 2-deep register prefetch, fused last-block mean.
//   ce[b]  = log(sum exp(logits[b,:])) - logits[b, labels[b]]
//   pred   = argmax (first occurrence); df = dis[lab,pred]+0.5
//   out[0] = mean(ce*df), out[1..B] = df
// Measured ceiling for this stream on this part: ~5.4 TB/s (occupancy,
// pipeline depth, issue order, and load path all falsified as levers).

#define CCOLS 40
#define TPB   128
#define WPB   4                        // warps per block
#define RPW   16                       // rows per warp-tile (2 lanes/row)
#define F4PT  (RPW * 10)               // 160 float4 = 2560 B per stage
#define GRIDB 1366                     // ~9.2 CTAs/SM, near-even tile split
#define NW    (GRIDB * WPB)            // 5464 warps

#define CP_CG16(dst, src) asm volatile("cp.async.cg.shared.global [%0], [%1], 16;" :: "r"(dst), "l"(src) : "memory")
#define CP_COMMIT()       asm volatile("cp.async.commit_group;" ::: "memory")
#define CP_WAIT1()        asm volatile("cp.async.wait_group 1;" ::: "memory")

__device__ float    g_partials[8192];
__device__ unsigned g_count;           // zero-init; last block resets

__global__ void __launch_bounds__(TPB, 10) hier_loss_r16(
    const float* __restrict__ logits,  // [B*40]
    const int*   __restrict__ labels,  // [B]
    const float* __restrict__ dis,     // [40*40]
    float*       __restrict__ out,     // [0] = loss
    float*       __restrict__ df_out,  // [B]
    float invB, int ntiles)            // ntiles = B/16
{
    __shared__ __align__(128) float4 tile[WPB][2][F4PT];   // 20480 B
    __shared__ float wsum[WPB];
    __shared__ int   isLast;

    const int tid  = threadIdx.x;
    const int wid  = tid >> 5;
    const int lane = tid & 31;
    const int half = lane & 1;         // 0: cols 0-19, 1: cols 20-39
    const int rrow = lane >> 1;        // row within tile (0..15)
    const int bid  = blockIdx.x;
    const int gw   = bid * WPB + wid;  // global warp id

    const int nmine = (ntiles - gw + NW - 1) / NW;   // 11 or 12 (balanced)

    const uint32_t t0 = (uint32_t)__cvta_generic_to_shared(&tile[wid][0][0]);

    auto issue = [&](int j) {          // warp-cooperative, coalesced
        const int s = j & 1;
        const long long t = gw + (long long)j * NW;
        const float4* src = (const float4*)logits + t * F4PT;
        const uint32_t dst = t0 + (uint32_t)s * (F4PT * 16);
        #pragma unroll
        for (int i = 0; i < 5; ++i) {
            int idx = i * 32 + lane;
            CP_CG16(dst + (uint32_t)idx * 16u, src + idx);
        }
    };

    auto lrow = [&](int j) -> long long {   // row owned by even lane, tile j
        return (gw + (long long)j * NW) * RPW + rrow;
    };

    int lab_q0 = 0, lab_q1 = 0;        // 2-deep label prefetch (even lanes)
    if (nmine > 0) {
        issue(0); CP_COMMIT();
        if (half == 0) lab_q0 = __ldcs(&labels[lrow(0)]);
    }
    if (nmine > 1) {
        issue(1); CP_COMMIT();
        if (half == 0) lab_q1 = __ldcs(&labels[lrow(1)]);
    }

    float acc = 0.0f;

    for (int j = 0; j < nmine; ++j) {
        const int s = j & 1;

        CP_WAIT1();                    // own oldest group complete
        __syncwarp();                  // cross-lane copy visibility (required)

        // lane covers floats [20*half, 20*half+20) of row rrow
        const float4* r   = &tile[wid][s][rrow * 10 + half * 5];
        const float*  row = (const float*)&tile[wid][s][rrow * 10];
        const int base = 20 * half;

        float m = -INFINITY, sum = 0.0f;
        int   am = base;
        #pragma unroll
        for (int i = 0; i < 5; ++i) {
            float4 v = r[i];
            if (v.x > m) { m = v.x; am = base + 4*i;   }
            if (v.y > m) { m = v.y; am = base + 4*i+1; }
            if (v.z > m) { m = v.z; am = base + 4*i+2; }
            if (v.w > m) { m = v.w; am = base + 4*i+3; }
            sum += (__expf(v.x) + __expf(v.y)) + (__expf(v.z) + __expf(v.w));
        }
        {   // pair merge (xor 1); tie -> smaller index = first occurrence
            float om = __shfl_xor_sync(0xffffffffu, m,  1);
            int   oa = __shfl_xor_sync(0xffffffffu, am, 1);
            if (om > m || (om == m && oa < am)) { m = om; am = oa; }
            sum += __shfl_xor_sync(0xffffffffu, sum, 1);
        }
        const float lse = __logf(sum);

        if (half == 0) {               // even lane finalizes its row
            const int lab = lab_q0;
            const float ce  = lse - row[lab];
            const float dfv = __ldg(&dis[lab * CCOLS + am]) + 0.5f;
            __stcs(&df_out[lrow(j)], dfv);
            acc += ce * dfv;
        }

        // rotate label queue; prefetch j+2 (hidden behind next tile's copy)
        lab_q0 = lab_q1;
        if (half == 0 && j + 2 < nmine) lab_q1 = __ldcs(&labels[lrow(j + 2)]);

        // warp is converged here: stage-s reads architecturally complete,
        // so refill needs no extra sync.
        if (j + 2 < nmine) issue(j + 2);
        CP_COMMIT();                   // uniform commits keep wait_group aligned
    }

    // ---- block reduction (deterministic) ----
    #pragma unroll
    for (int o = 16; o > 0; o >>= 1)
        acc += __shfl_down_sync(0xffffffffu, acc, o);
    if (lane == 0) wsum[wid] = acc;
    __syncthreads();
    if (tid == 0) {
        g_partials[bid] = (wsum[0] + wsum[1]) + (wsum[2] + wsum[3]);
        __threadfence();
        isLast = (atomicAdd(&g_count, 1u) == (unsigned)(GRIDB - 1));
    }
    __syncthreads();

    // ---- last-block-done final mean: independent unrolled loads ----
    if (isLast) {
        float part[11];                          // ceil(1366/128) = 11
        #pragma unroll
        for (int k = 0; k < 11; ++k) {
            int i = tid + k * TPB;
            part[k] = (i < GRIDB) ? g_partials[i] : 0.0f;
        }
        float t = 0.0f;
        #pragma unroll
        for (int k = 0; k < 11; ++k) t += part[k];

        #pragma unroll
        for (int o = 16; o > 0; o >>= 1)
            t += __shfl_down_sync(0xffffffffu, t, o);
        __shared__ float fsum[WPB];
        if (lane == 0) fsum[wid] = t;
        __syncthreads();
        if (tid == 0) {
            out[0] = ((fsum[0] + fsum[1]) + (fsum[2] + fsum[3])) * invB;
            g_count = 0;               // reset for graph replay
        }
    }
}

extern "C" void kernel_launch(void* const* d_in, const int* in_sizes, int n_in,
                              void* d_out, int out_size)
{
    const float* logits = (const float*)d_in[0];
    const int*   labels = (const int*)d_in[1];
    const float* dis    = (const float*)d_in[2];
    float* out = (float*)d_out;

    const long long B = (long long)in_sizes[1];     // 1048576
    const int ntiles = (int)(B / RPW);              // 65536

    const int off = out_size - (int)B;              // [loss, df...] layout
    float* dfo = out + (off > 0 ? off : 0);

    hier_loss_r16<<<GRIDB, TPB>>>(logits, labels, dis, out, dfo,
                                  1.0f / (float)B, ntiles);
}